// round 16
// baseline (speedup 1.0000x reference)
#include <cuda_runtime.h>
#include <math.h>

#define HEADS 8
#define DIM 64
#define DH 64
#define DK 24
#define DHK 3
#define B 4
#define H 128
#define W 128
#define NTOK (H*W)           // 16384

typedef unsigned long long ull;

// ---------------- scratch ---------------------------------------------------
__device__ __align__(16) float g_kinp[B * DK * H * W];  // planar [b][ch][y][x]
__device__ __align__(16) float g_t1[B * DK * H * W];    // gelu(conv1) planar
__device__ __align__(16) float g_SW[2 * B * 24 * 64];   // S then W2 (zero-init)

// ---------------- packed f32x2 helpers -------------------------------------
__device__ __forceinline__ ull pack2(float lo, float hi) {
    ull r; asm("mov.b64 %0, {%1,%2};" : "=l"(r) : "f"(lo), "f"(hi)); return r;
}
__device__ __forceinline__ void unpack2(ull v, float& lo, float& hi) {
    asm("mov.b64 {%0,%1}, %2;" : "=f"(lo), "=f"(hi) : "l"(v));
}
__device__ __forceinline__ void fma2(ull& d, ull a, ull b) {
    asm("fma.rn.f32x2 %0, %1, %2, %0;" : "+l"(d) : "l"(a), "l"(b));
}
__device__ __forceinline__ ull add2(ull a, ull b) {
    ull r; asm("add.rn.f32x2 %0, %1, %2;" : "=l"(r) : "l"(a), "l"(b)); return r;
}

__device__ __forceinline__ float gelu_exact(float x) {
    return 0.5f * x * (1.0f + erff(x * 0.70710678118654752f));
}

// ===========================================================================
// K1: k_inp = illu_map @ Wk (planar write) + S[b] += k_inp^T @ x
// HALF-ROW blocks: grid (256, B), 64 tokens per block, smem ~25KB,
// 6 blocks/SM (42-reg cap) -> 48 warps/SM for latency hiding.
// Same phase structure as the proven round-7 kernel.
// ===========================================================================
__global__ __launch_bounds__(256, 6) void k1_kinp_S(
    const float* __restrict__ x, const float* __restrict__ im,
    const float* __restrict__ Wk)
{
    __shared__ __align__(16) float wk_s[576];
    __shared__ __align__(16) float k_s[64 * 25];
    __shared__ __align__(16) float buf[64 * 64];    // im_s then x_s

    const int tid = threadIdx.x;
    const int b = blockIdx.y;
    const int row = blockIdx.x >> 1;
    const int xoff = (blockIdx.x & 1) * 64;
    const int t0 = b * NTOK + row * 128 + xoff;

    // zero W2 slice (6 floats per block, 1024 blocks cover 6144 floats)
    {
        int bid = blockIdx.y * 256 + blockIdx.x;
        if (tid < 6) g_SW[6144 + bid * 6 + tid] = 0.f;
    }

    for (int i = tid; i < 576; i += 256) wk_s[i] = Wk[i];
    {
        const float* img = im + (size_t)t0 * 24;
        #pragma unroll
        for (int i = tid; i < 1536; i += 256) {
            int tok = i / 24, ci = i - tok * 24;
            buf[tok * 25 + ci] = img[i];
        }
    }
    __syncthreads();

    // k_inp: 4 threads per token (each does 6 output channels)
    {
        const int tok = tid >> 2;
        const int j0 = (tid & 3) * 6;
        float acc[6];
        #pragma unroll
        for (int j = 0; j < 6; j++) acc[j] = 0.f;
        #pragma unroll 4
        for (int ci = 0; ci < 24; ci++) {
            float inv = buf[tok * 25 + ci];
            const float2* wp2 = (const float2*)&wk_s[ci * 24 + j0];
            float2 w0 = wp2[0], w1 = wp2[1], w2 = wp2[2];
            acc[0] += inv * w0.x; acc[1] += inv * w0.y;
            acc[2] += inv * w1.x; acc[3] += inv * w1.y;
            acc[4] += inv * w2.x; acc[5] += inv * w2.y;
        }
        #pragma unroll
        for (int j = 0; j < 6; j++) k_s[tok * 25 + j0 + j] = acc[j];
    }
    __syncthreads();

    // stage x into buf (overwrites im) + planar k_inp write (coalesced)
    {
        const float4* xg = (const float4*)(x + (size_t)t0 * 64);
        float4* xs4 = (float4*)buf;
        #pragma unroll
        for (int i = tid; i < 1024; i += 256) xs4[i] = xg[i];
    }
    {
        #pragma unroll
        for (int i = tid; i < 1536; i += 256) {
            int ch = i >> 6, xx = i & 63;
            g_kinp[(((size_t)b * 24 + ch) * H + row) * W + xoff + xx] = k_s[xx * 25 + ch];
        }
    }
    __syncthreads();

    // S partial: warp jj owns j = jj*3+{0,1,2}; lane cc owns c = cc*2+{0,1}
    {
        const int jj = tid >> 5;
        const int cc = tid & 31;
        ull s0 = 0, s1 = 0, s2 = 0;
        const ull* xp = (const ull*)buf;
        #pragma unroll 4
        for (int t = 0; t < 64; t++) {
            ull xv = xp[t * 32 + cc];
            float ka = k_s[t * 25 + jj * 3 + 0];
            float kb = k_s[t * 25 + jj * 3 + 1];
            float kc = k_s[t * 25 + jj * 3 + 2];
            fma2(s0, pack2(ka, ka), xv);
            fma2(s1, pack2(kb, kb), xv);
            fma2(s2, pack2(kc, kc), xv);
        }
        float lo, hi;
        float* Sg = g_SW + b * 1536;
        unpack2(s0, lo, hi);
        atomicAdd(&Sg[(jj * 3 + 0) * 64 + cc * 2], lo);
        atomicAdd(&Sg[(jj * 3 + 0) * 64 + cc * 2 + 1], hi);
        unpack2(s1, lo, hi);
        atomicAdd(&Sg[(jj * 3 + 1) * 64 + cc * 2], lo);
        atomicAdd(&Sg[(jj * 3 + 1) * 64 + cc * 2 + 1], hi);
        unpack2(s2, lo, hi);
        atomicAdd(&Sg[(jj * 3 + 2) * 64 + cc * 2], lo);
        atomicAdd(&Sg[(jj * 3 + 2) * 64 + cc * 2 + 1], hi);
    }
}

// ===========================================================================
// LDG+shfl conv (round 13, measured)
// ===========================================================================
__device__ __forceinline__ void conv_ldg(
    const float* __restrict__ src, const ull* wsp,
    int b, int y, int ocp, int lane, ull acc[4])
{
    const int g = ocp >> 2;
    const int oc0 = ocp * 2;
    #pragma unroll
    for (int r = 0; r < 3; r++) {
        const int gy = y - 1 + r;
        if ((unsigned)gy >= (unsigned)H) continue;
        const float* rowbase = src + (((size_t)b * 24 + g * 8) * H + gy) * W + lane * 4;
        #pragma unroll
        for (int i = 0; i < 8; i++) {
            float4 Bv = __ldg((const float4*)(rowbase + i * NTOK));
            float left = __shfl_up_sync(~0u, Bv.w, 1);
            if (lane == 0) left = 0.f;
            float right = __shfl_down_sync(~0u, Bv.x, 1);
            if (lane == 31) right = 0.f;
            ull P0 = pack2(left, Bv.x);
            ull P1 = pack2(Bv.x, Bv.y);
            ull P2 = pack2(Bv.y, Bv.z);
            ull P3 = pack2(Bv.z, Bv.w);
            ull P4 = pack2(Bv.w, right);
            const int tb = (i * 9 + r * 3) * 24 + oc0;
            {
                ulonglong2 wv = *(const ulonglong2*)&wsp[tb];
                fma2(acc[0], wv.x, P0); fma2(acc[1], wv.x, P2);
                fma2(acc[2], wv.y, P0); fma2(acc[3], wv.y, P2);
            }
            {
                ulonglong2 wv = *(const ulonglong2*)&wsp[tb + 24];
                fma2(acc[0], wv.x, P1); fma2(acc[1], wv.x, P3);
                fma2(acc[2], wv.y, P1); fma2(acc[3], wv.y, P3);
            }
            {
                ulonglong2 wv = *(const ulonglong2*)&wsp[tb + 48];
                fma2(acc[0], wv.x, P2); fma2(acc[1], wv.x, P4);
                fma2(acc[2], wv.y, P2); fma2(acc[3], wv.y, P4);
            }
        }
    }
}

// ===========================================================================
// K4A+K2 merged: grid (129, B), block 384, 4 blocks/SM (42-reg cap).
//  blockIdx.x < 128 : conv1 + GELU -> g_t1 + fea L2-prefetch.
//  blockIdx.x == 128: attention role for heads (2*b, 2*b+1).
// (round 15 body, measured good)
// ===========================================================================
__global__ __launch_bounds__(384, 4) void k4a_conv1_k2(
    const float* __restrict__ c1w, const float* __restrict__ fea,
    const float* __restrict__ Wq, const float* __restrict__ Wv,
    const float* __restrict__ Wp, const float* __restrict__ rescale)
{
    __shared__ __align__(16) float smu[6536];
    const int tid = threadIdx.x;

    if (blockIdx.x < 128) {
        ull* wsp = (ull*)smu;
        const int b = blockIdx.y;
        const int y = blockIdx.x;

        for (int i = tid; i < 1728; i += 384) {
            int oc = i / 72, r2 = i - oc * 72;
            float w = c1w[i];
            wsp[r2 * 24 + oc] = pack2(w, w);
        }
        __syncthreads();

        const int ocp = tid >> 5, lane = tid & 31;
        ull acc[4] = {0ull, 0ull, 0ull, 0ull};
        conv_ldg(g_kinp, wsp, b, y, ocp, lane, acc);

        float v[8];
        unpack2(acc[0], v[0], v[1]); unpack2(acc[1], v[2], v[3]);
        unpack2(acc[2], v[4], v[5]); unpack2(acc[3], v[6], v[7]);
        #pragma unroll
        for (int q = 0; q < 8; q++) v[q] = gelu_exact(v[q]);
        const int oc0 = ocp * 2;
        float4* d0 = (float4*)(g_t1 + (((size_t)b * 24 + oc0) * H + y) * W + lane * 4);
        float4* d1 = (float4*)(g_t1 + (((size_t)b * 24 + oc0 + 1) * H + y) * W + lane * 4);
        *d0 = make_float4(v[0], v[1], v[2], v[3]);
        *d1 = make_float4(v[4], v[5], v[6], v[7]);

        if (tid < 256) {
            const char* fp = (const char*)(fea +
                ((size_t)b * NTOK + (size_t)y * W) * 64) + tid * 128;
            asm volatile("prefetch.global.L2 [%0];" :: "l"(fp));
        }
        return;
    }

    // ---- attention role: two heads sequentially ----
    float* wqv_s = smu;            // [64][65]
    float* s_S   = smu + 4160;     // [4][3][64]
    float* s_A   = smu + 4928;     // [4][3][64]
    float* s_M   = smu + 5696;     // [4*64][3]
    float* wp_s  = smu + 6464;     // [3][24]

    for (int hh = 0; hh < 2; hh++) {
        const int h = blockIdx.y * 2 + hh;

        for (int i = tid; i < 4096; i += 384) {
            int c = i >> 6, d = i & 63;
            wqv_s[c * 65 + d] = Wq[c * 512 + h * 64 + d];
        }
        for (int i = tid; i < 768; i += 384) {
            int b2 = i / 192, rem = i - b2 * 192;
            s_S[i] = g_SW[b2 * 1536 + h * 3 * 64 + rem];
        }
        if (tid < 72) {
            int k = tid / 24, o = tid - k * 24;
            wp_s[tid] = Wp[(k * 8 + h) * 24 + o];
        }
        __syncthreads();

        for (int i = tid; i < 768; i += 384) {
            int b2 = i / 192, rem = i - b2 * 192;
            g_SW[b2 * 1536 + h * 3 * 64 + rem] = 0.f;
        }

        const int b = tid >> 6;
        const int d = tid & 63;
        const float sc = rescale[h] * 0.125f;

        if (tid < 256) {
            float a0 = 0.f, a1 = 0.f, a2 = 0.f;
            const float* Sb = s_S + b * 192;
            #pragma unroll 8
            for (int c = 0; c < 64; c++) {
                float wq = wqv_s[c * 65 + d];
                a0 += Sb[c] * wq;
                a1 += Sb[64 + c] * wq;
                a2 += Sb[128 + c] * wq;
            }
            s_A[(b * 3 + 0) * 64 + d] = a0 * sc;
            s_A[(b * 3 + 1) * 64 + d] = a1 * sc;
            s_A[(b * 3 + 2) * 64 + d] = a2 * sc;
        }
        __syncthreads();

        if (tid < 256) {
            const int wid = tid >> 5, lane = tid & 31;
            for (int rowi = wid; rowi < 12; rowi += 8) {
                float v0 = s_A[rowi * 64 + lane];
                float v1 = s_A[rowi * 64 + 32 + lane];
                float m = fmaxf(v0, v1);
                #pragma unroll
                for (int off = 16; off; off >>= 1) m = fmaxf(m, __shfl_xor_sync(~0u, m, off));
                float e0 = __expf(v0 - m), e1 = __expf(v1 - m);
                float s2 = e0 + e1;
                #pragma unroll
                for (int off = 16; off; off >>= 1) s2 += __shfl_xor_sync(~0u, s2, off);
                float inv = 1.0f / s2;
                s_A[rowi * 64 + lane] = e0 * inv;
                s_A[rowi * 64 + 32 + lane] = e1 * inv;
            }
        }
        __syncthreads();

        for (int i = tid; i < 4096; i += 384) {
            int c = i >> 6, dd = i & 63;
            wqv_s[c * 65 + dd] = Wv[c * 512 + h * 64 + dd];
        }
        __syncthreads();

        if (tid < 256) {
            const int c = tid & 63;
            float m0 = 0.f, m1 = 0.f, m2 = 0.f;
            const float* Ab = s_A + b * 192;
            const float* wvr = wqv_s + c * 65;
            #pragma unroll 8
            for (int dd = 0; dd < 64; dd++) {
                float wv = wvr[dd];
                m0 += wv * Ab[dd];
                m1 += wv * Ab[64 + dd];
                m2 += wv * Ab[128 + dd];
            }
            s_M[(b * 64 + c) * 3 + 0] = m0;
            s_M[(b * 64 + c) * 3 + 1] = m1;
            s_M[(b * 64 + c) * 3 + 2] = m2;
        }
        __syncthreads();

        if (tid < 256) {
            const int c = tid & 63;
            const float* mrow = &s_M[(b * 64 + c) * 3];
            float m0 = mrow[0], m1 = mrow[1], m2 = mrow[2];
            float* W2g = g_SW + 6144 + b * 1536 + c * 24;
            #pragma unroll
            for (int o = 0; o < 24; o++) {
                float v = m0 * wp_s[o] + m1 * wp_s[24 + o] + m2 * wp_s[48 + o];
                atomicAdd(&W2g[o], v);
            }
        }
        __syncthreads();
    }
}

// ===========================================================================
// K4B: conv2 (LDG from g_t1, L2-hot) + projection fea@W2+bp + store.
// (round 15 body, measured good)
// ===========================================================================
__global__ __launch_bounds__(384, 4) void k4b_conv2_proj(
    const float* __restrict__ fea, const float* __restrict__ bp,
    const float* __restrict__ c2w, float* __restrict__ out)
{
    __shared__ __align__(16) ull wsp[1728];
    __shared__ __align__(16) float c2s[24 * 132];
    __shared__ __align__(16) float W2s[1536];
    __shared__ float bps[32];

    const int tid = threadIdx.x;
    const int b = blockIdx.y;
    const int y = blockIdx.x;

    for (int i = tid; i < 1728; i += 384) {
        int oc = i / 72, r2 = i - oc * 72;
        float w = c2w[i];
        wsp[r2 * 24 + oc] = pack2(w, w);
    }
    {
        const float* w2g = g_SW + 6144 + b * 1536;
        for (int i = tid; i < 1536; i += 384) W2s[i] = w2g[i];
    }
    if (tid < 24) bps[tid] = bp[tid];
    __syncthreads();

    const int ocp = tid >> 5, lane = tid & 31;
    ull cacc[4] = {0ull, 0ull, 0ull, 0ull};
    conv_ldg(g_t1, wsp, b, y, ocp, lane, cacc);

    {
        const int oc0 = ocp * 2;
        float cv[8];
        unpack2(cacc[0], cv[0], cv[1]); unpack2(cacc[1], cv[2], cv[3]);
        unpack2(cacc[2], cv[4], cv[5]); unpack2(cacc[3], cv[6], cv[7]);
        *(float4*)(c2s + oc0 * 132 + lane * 4) = make_float4(cv[0], cv[1], cv[2], cv[3]);
        *(float4*)(c2s + (oc0 + 1) * 132 + lane * 4) = make_float4(cv[4], cv[5], cv[6], cv[7]);
    }
    __syncthreads();

    if (tid < 256) {
        const int px = tid >> 1;
        const int ob = (tid & 1) * 12;
        ull acc[6];
        #pragma unroll
        for (int m = 0; m < 6; m++) acc[m] = 0ull;
        const float4* fea4 = (const float4*)(fea +
            ((size_t)b * NTOK + (size_t)y * W + px) * 64);
        #pragma unroll 4
        for (int c4 = 0; c4 < 16; c4++) {
            float4 f = fea4[c4];
            float fe[4] = {f.x, f.y, f.z, f.w};
            #pragma unroll
            for (int e = 0; e < 4; e++) {
                ull f2 = pack2(fe[e], fe[e]);
                const ulonglong2* wrow =
                    (const ulonglong2*)(W2s + (c4 * 4 + e) * 24 + ob);
                ulonglong2 wa = wrow[0];
                fma2(acc[0], wa.x, f2);
                fma2(acc[1], wa.y, f2);
                ulonglong2 wb = wrow[1];
                fma2(acc[2], wb.x, f2);
                fma2(acc[3], wb.y, f2);
                ulonglong2 wc = wrow[2];
                fma2(acc[4], wc.x, f2);
                fma2(acc[5], wc.y, f2);
            }
        }
        float res[12];
        #pragma unroll
        for (int m = 0; m < 6; m++) {
            float lo, hi; unpack2(acc[m], lo, hi);
            res[2 * m] = lo + bps[ob + 2 * m];
            res[2 * m + 1] = hi + bps[ob + 2 * m + 1];
        }
        #pragma unroll
        for (int ch = 0; ch < 12; ch++)
            res[ch] += c2s[(ob + ch) * 132 + px];
        float4* og = (float4*)(out +
            ((size_t)b * NTOK + (size_t)y * W + px) * 24 + ob);
        og[0] = make_float4(res[0], res[1], res[2], res[3]);
        og[1] = make_float4(res[4], res[5], res[6], res[7]);
        og[2] = make_float4(res[8], res[9], res[10], res[11]);
    }
}

// ===========================================================================
extern "C" void kernel_launch(void* const* d_in, const int* in_sizes, int n_in,
                              void* d_out, int out_size)
{
    const float* x = (const float*)d_in[0];
    const float* fea = (const float*)d_in[1];
    const float* im = (const float*)d_in[2];
    const float* Wq = (const float*)d_in[3];
    const float* Wk = (const float*)d_in[4];
    const float* Wv = (const float*)d_in[5];
    const float* rescale = (const float*)d_in[6];
    const float* Wp = (const float*)d_in[7];
    const float* bp = (const float*)d_in[8];
    const float* c1w = (const float*)d_in[9];
    const float* c2w = (const float*)d_in[10];
    float* out = (float*)d_out;

    k1_kinp_S<<<dim3(256, B), 256>>>(x, im, Wk);
    k4a_conv1_k2<<<dim3(129, B), 384>>>(c1w, fea, Wq, Wv, Wp, rescale);
    k4b_conv2_proj<<<dim3(128, B), 384>>>(fea, bp, c2w, out);
}

// round 17
// speedup vs baseline: 1.1294x; 1.1294x over previous
#include <cuda_runtime.h>
#include <math.h>

#define HEADS 8
#define DIM 64
#define DH 64
#define DK 24
#define DHK 3
#define B 4
#define H 128
#define W 128
#define NTOK (H*W)           // 16384

typedef unsigned long long ull;

// ---------------- scratch ---------------------------------------------------
__device__ __align__(16) float g_kinp[B * DK * H * W];  // planar [b][ch][y][x]
__device__ __align__(16) float g_t1[B * DK * H * W];    // gelu(conv1) planar
__device__ __align__(16) float g_SW[2 * B * 24 * 64];   // S then W2 (zero-init)

// ---------------- packed f32x2 helpers -------------------------------------
__device__ __forceinline__ ull pack2(float lo, float hi) {
    ull r; asm("mov.b64 %0, {%1,%2};" : "=l"(r) : "f"(lo), "f"(hi)); return r;
}
__device__ __forceinline__ void unpack2(ull v, float& lo, float& hi) {
    asm("mov.b64 {%0,%1}, %2;" : "=f"(lo), "=f"(hi) : "l"(v));
}
__device__ __forceinline__ void fma2(ull& d, ull a, ull b) {
    asm("fma.rn.f32x2 %0, %1, %2, %0;" : "+l"(d) : "l"(a), "l"(b));
}
__device__ __forceinline__ ull add2(ull a, ull b) {
    ull r; asm("add.rn.f32x2 %0, %1, %2;" : "=l"(r) : "l"(a), "l"(b)); return r;
}

__device__ __forceinline__ float gelu_exact(float x) {
    return 0.5f * x * (1.0f + erff(x * 0.70710678118654752f));
}

// ===========================================================================
// K1: k_inp = illu_map @ Wk (planar write) + S[b] += k_inp^T @ x
// (round 7/15 body — measured 21.5us across 5 rounds; do not touch)
// ===========================================================================
__global__ __launch_bounds__(256, 4) void k1_kinp_S(
    const float* __restrict__ x, const float* __restrict__ im,
    const float* __restrict__ Wk)
{
    __shared__ __align__(16) float wk_s[576];
    __shared__ __align__(16) float k_s[128 * 25];
    __shared__ __align__(16) float buf[128 * 64];   // im_s then x_s

    const int tid = threadIdx.x;
    const int b = blockIdx.y;
    const int row = blockIdx.x;
    const int t0 = b * NTOK + row * 128;

    {
        int bid = blockIdx.y * 128 + blockIdx.x;
        if (tid < 12) g_SW[6144 + bid * 12 + tid] = 0.f;
    }

    for (int i = tid; i < 576; i += 256) wk_s[i] = Wk[i];
    {
        const float* img = im + (size_t)t0 * 24;
        #pragma unroll
        for (int i = tid; i < 3072; i += 256) {
            int tok = i / 24, ci = i - tok * 24;
            buf[tok * 25 + ci] = img[i];
        }
    }
    __syncthreads();

    {
        const int tok = tid >> 1;
        const int j0 = (tid & 1) * 12;
        float acc[12];
        #pragma unroll
        for (int j = 0; j < 12; j++) acc[j] = 0.f;
        #pragma unroll 4
        for (int ci = 0; ci < 24; ci++) {
            float inv = buf[tok * 25 + ci];
            const float4* wp4 = (const float4*)&wk_s[ci * 24 + j0];
            float4 w0 = wp4[0], w1 = wp4[1], w2 = wp4[2];
            acc[0] += inv * w0.x; acc[1] += inv * w0.y; acc[2] += inv * w0.z; acc[3] += inv * w0.w;
            acc[4] += inv * w1.x; acc[5] += inv * w1.y; acc[6] += inv * w1.z; acc[7] += inv * w1.w;
            acc[8] += inv * w2.x; acc[9] += inv * w2.y; acc[10] += inv * w2.z; acc[11] += inv * w2.w;
        }
        #pragma unroll
        for (int j = 0; j < 12; j++) k_s[tok * 25 + j0 + j] = acc[j];
    }
    __syncthreads();

    {
        const float4* xg = (const float4*)(x + (size_t)t0 * 64);
        float4* xs4 = (float4*)buf;
        #pragma unroll
        for (int i = tid; i < 2048; i += 256) xs4[i] = xg[i];
    }
    {
        #pragma unroll
        for (int i = tid; i < 3072; i += 256) {
            int ch = i >> 7, xx = i & 127;
            g_kinp[(((size_t)b * 24 + ch) * H + row) * W + xx] = k_s[xx * 25 + ch];
        }
    }
    __syncthreads();

    {
        const int jj = tid >> 5;
        const int cc = tid & 31;
        ull s0 = 0, s1 = 0, s2 = 0;
        const ull* xp = (const ull*)buf;
        #pragma unroll 4
        for (int t = 0; t < 128; t++) {
            ull xv = xp[t * 32 + cc];
            float ka = k_s[t * 25 + jj * 3 + 0];
            float kb = k_s[t * 25 + jj * 3 + 1];
            float kc = k_s[t * 25 + jj * 3 + 2];
            fma2(s0, pack2(ka, ka), xv);
            fma2(s1, pack2(kb, kb), xv);
            fma2(s2, pack2(kc, kc), xv);
        }
        float lo, hi;
        float* Sg = g_SW + b * 1536;
        unpack2(s0, lo, hi);
        atomicAdd(&Sg[(jj * 3 + 0) * 64 + cc * 2], lo);
        atomicAdd(&Sg[(jj * 3 + 0) * 64 + cc * 2 + 1], hi);
        unpack2(s1, lo, hi);
        atomicAdd(&Sg[(jj * 3 + 1) * 64 + cc * 2], lo);
        atomicAdd(&Sg[(jj * 3 + 1) * 64 + cc * 2 + 1], hi);
        unpack2(s2, lo, hi);
        atomicAdd(&Sg[(jj * 3 + 2) * 64 + cc * 2], lo);
        atomicAdd(&Sg[(jj * 3 + 2) * 64 + cc * 2 + 1], hi);
    }
}

// ===========================================================================
// LDG+shfl conv (round 13, measured)
// ===========================================================================
__device__ __forceinline__ void conv_ldg(
    const float* __restrict__ src, const ull* wsp,
    int b, int y, int ocp, int lane, ull acc[4])
{
    const int g = ocp >> 2;
    const int oc0 = ocp * 2;
    #pragma unroll
    for (int r = 0; r < 3; r++) {
        const int gy = y - 1 + r;
        if ((unsigned)gy >= (unsigned)H) continue;
        const float* rowbase = src + (((size_t)b * 24 + g * 8) * H + gy) * W + lane * 4;
        #pragma unroll
        for (int i = 0; i < 8; i++) {
            float4 Bv = __ldg((const float4*)(rowbase + i * NTOK));
            float left = __shfl_up_sync(~0u, Bv.w, 1);
            if (lane == 0) left = 0.f;
            float right = __shfl_down_sync(~0u, Bv.x, 1);
            if (lane == 31) right = 0.f;
            ull P0 = pack2(left, Bv.x);
            ull P1 = pack2(Bv.x, Bv.y);
            ull P2 = pack2(Bv.y, Bv.z);
            ull P3 = pack2(Bv.z, Bv.w);
            ull P4 = pack2(Bv.w, right);
            const int tb = (i * 9 + r * 3) * 24 + oc0;
            {
                ulonglong2 wv = *(const ulonglong2*)&wsp[tb];
                fma2(acc[0], wv.x, P0); fma2(acc[1], wv.x, P2);
                fma2(acc[2], wv.y, P0); fma2(acc[3], wv.y, P2);
            }
            {
                ulonglong2 wv = *(const ulonglong2*)&wsp[tb + 24];
                fma2(acc[0], wv.x, P1); fma2(acc[1], wv.x, P3);
                fma2(acc[2], wv.y, P1); fma2(acc[3], wv.y, P3);
            }
            {
                ulonglong2 wv = *(const ulonglong2*)&wsp[tb + 48];
                fma2(acc[0], wv.x, P2); fma2(acc[1], wv.x, P4);
                fma2(acc[2], wv.y, P2); fma2(acc[3], wv.y, P4);
            }
        }
    }
}

// ===========================================================================
// K4A+K2 merged: grid (130, B), block 384, 4 blocks/SM (42-reg cap).
//  blockIdx.x < 128      : conv1 + GELU -> g_t1 + fea L2-prefetch.
//  blockIdx.x in {128,129}: attention role, ONE head = 2*b + (x-128)
//                           (halved critical path vs 2-head blocks).
// ===========================================================================
__global__ __launch_bounds__(384, 4) void k4a_conv1_k2(
    const float* __restrict__ c1w, const float* __restrict__ fea,
    const float* __restrict__ Wq, const float* __restrict__ Wv,
    const float* __restrict__ Wp, const float* __restrict__ rescale)
{
    __shared__ __align__(16) float smu[6536];
    const int tid = threadIdx.x;

    if (blockIdx.x < 128) {
        ull* wsp = (ull*)smu;
        const int b = blockIdx.y;
        const int y = blockIdx.x;

        for (int i = tid; i < 1728; i += 384) {
            int oc = i / 72, r2 = i - oc * 72;
            float w = c1w[i];
            wsp[r2 * 24 + oc] = pack2(w, w);
        }
        __syncthreads();

        const int ocp = tid >> 5, lane = tid & 31;
        ull acc[4] = {0ull, 0ull, 0ull, 0ull};
        conv_ldg(g_kinp, wsp, b, y, ocp, lane, acc);

        float v[8];
        unpack2(acc[0], v[0], v[1]); unpack2(acc[1], v[2], v[3]);
        unpack2(acc[2], v[4], v[5]); unpack2(acc[3], v[6], v[7]);
        #pragma unroll
        for (int q = 0; q < 8; q++) v[q] = gelu_exact(v[q]);
        const int oc0 = ocp * 2;
        float4* d0 = (float4*)(g_t1 + (((size_t)b * 24 + oc0) * H + y) * W + lane * 4);
        float4* d1 = (float4*)(g_t1 + (((size_t)b * 24 + oc0 + 1) * H + y) * W + lane * 4);
        *d0 = make_float4(v[0], v[1], v[2], v[3]);
        *d1 = make_float4(v[4], v[5], v[6], v[7]);

        if (tid < 256) {
            const char* fp = (const char*)(fea +
                ((size_t)b * NTOK + (size_t)y * W) * 64) + tid * 128;
            asm volatile("prefetch.global.L2 [%0];" :: "l"(fp));
        }
        return;
    }

    // ---- attention role: single head ----
    float* wqv_s = smu;            // [64][65]
    float* s_S   = smu + 4160;     // [4][3][64]
    float* s_A   = smu + 4928;     // [4][3][64]
    float* s_M   = smu + 5696;     // [4*64][3]
    float* wp_s  = smu + 6464;     // [3][24]

    const int h = blockIdx.y * 2 + (blockIdx.x - 128);

    for (int i = tid; i < 4096; i += 384) {
        int c = i >> 6, d = i & 63;
        wqv_s[c * 65 + d] = Wq[c * 512 + h * 64 + d];
    }
    for (int i = tid; i < 768; i += 384) {
        int b2 = i / 192, rem = i - b2 * 192;
        s_S[i] = g_SW[b2 * 1536 + h * 3 * 64 + rem];
    }
    if (tid < 72) {
        int k = tid / 24, o = tid - k * 24;
        wp_s[tid] = Wp[(k * 8 + h) * 24 + o];
    }
    __syncthreads();

    // zero this head's S rows for the next replay (smem copy staged above)
    for (int i = tid; i < 768; i += 384) {
        int b2 = i / 192, rem = i - b2 * 192;
        g_SW[b2 * 1536 + h * 3 * 64 + rem] = 0.f;
    }

    const int b = tid >> 6;
    const int d = tid & 63;
    const float sc = rescale[h] * 0.125f;

    if (tid < 256) {
        float a0 = 0.f, a1 = 0.f, a2 = 0.f;
        const float* Sb = s_S + b * 192;
        #pragma unroll 8
        for (int c = 0; c < 64; c++) {
            float wq = wqv_s[c * 65 + d];
            a0 += Sb[c] * wq;
            a1 += Sb[64 + c] * wq;
            a2 += Sb[128 + c] * wq;
        }
        s_A[(b * 3 + 0) * 64 + d] = a0 * sc;
        s_A[(b * 3 + 1) * 64 + d] = a1 * sc;
        s_A[(b * 3 + 2) * 64 + d] = a2 * sc;
    }
    __syncthreads();

    if (tid < 256) {
        const int wid = tid >> 5, lane = tid & 31;
        for (int rowi = wid; rowi < 12; rowi += 8) {
            float v0 = s_A[rowi * 64 + lane];
            float v1 = s_A[rowi * 64 + 32 + lane];
            float m = fmaxf(v0, v1);
            #pragma unroll
            for (int off = 16; off; off >>= 1) m = fmaxf(m, __shfl_xor_sync(~0u, m, off));
            float e0 = __expf(v0 - m), e1 = __expf(v1 - m);
            float s2 = e0 + e1;
            #pragma unroll
            for (int off = 16; off; off >>= 1) s2 += __shfl_xor_sync(~0u, s2, off);
            float inv = 1.0f / s2;
            s_A[rowi * 64 + lane] = e0 * inv;
            s_A[rowi * 64 + 32 + lane] = e1 * inv;
        }
    }
    __syncthreads();

    for (int i = tid; i < 4096; i += 384) {
        int c = i >> 6, dd = i & 63;
        wqv_s[c * 65 + dd] = Wv[c * 512 + h * 64 + dd];
    }
    __syncthreads();

    if (tid < 256) {
        const int c = tid & 63;
        float m0 = 0.f, m1 = 0.f, m2 = 0.f;
        const float* Ab = s_A + b * 192;
        const float* wvr = wqv_s + c * 65;
        #pragma unroll 8
        for (int dd = 0; dd < 64; dd++) {
            float wv = wvr[dd];
            m0 += wv * Ab[dd];
            m1 += wv * Ab[64 + dd];
            m2 += wv * Ab[128 + dd];
        }
        s_M[(b * 64 + c) * 3 + 0] = m0;
        s_M[(b * 64 + c) * 3 + 1] = m1;
        s_M[(b * 64 + c) * 3 + 2] = m2;
    }
    __syncthreads();

    if (tid < 256) {
        const int c = tid & 63;
        const float* mrow = &s_M[(b * 64 + c) * 3];
        float m0 = mrow[0], m1 = mrow[1], m2 = mrow[2];
        float* W2g = g_SW + 6144 + b * 1536 + c * 24;
        #pragma unroll
        for (int o = 0; o < 24; o++) {
            float v = m0 * wp_s[o] + m1 * wp_s[24 + o] + m2 * wp_s[48 + o];
            atomicAdd(&W2g[o], v);
        }
    }
}

// ===========================================================================
// K4B: conv2 (LDG from g_t1, L2-hot) + projection fea@W2+bp + store.
// (round 15 body, measured good)
// ===========================================================================
__global__ __launch_bounds__(384, 4) void k4b_conv2_proj(
    const float* __restrict__ fea, const float* __restrict__ bp,
    const float* __restrict__ c2w, float* __restrict__ out)
{
    __shared__ __align__(16) ull wsp[1728];
    __shared__ __align__(16) float c2s[24 * 132];
    __shared__ __align__(16) float W2s[1536];
    __shared__ float bps[32];

    const int tid = threadIdx.x;
    const int b = blockIdx.y;
    const int y = blockIdx.x;

    for (int i = tid; i < 1728; i += 384) {
        int oc = i / 72, r2 = i - oc * 72;
        float w = c2w[i];
        wsp[r2 * 24 + oc] = pack2(w, w);
    }
    {
        const float* w2g = g_SW + 6144 + b * 1536;
        for (int i = tid; i < 1536; i += 384) W2s[i] = w2g[i];
    }
    if (tid < 24) bps[tid] = bp[tid];
    __syncthreads();

    const int ocp = tid >> 5, lane = tid & 31;
    ull cacc[4] = {0ull, 0ull, 0ull, 0ull};
    conv_ldg(g_t1, wsp, b, y, ocp, lane, cacc);

    {
        const int oc0 = ocp * 2;
        float cv[8];
        unpack2(cacc[0], cv[0], cv[1]); unpack2(cacc[1], cv[2], cv[3]);
        unpack2(cacc[2], cv[4], cv[5]); unpack2(cacc[3], cv[6], cv[7]);
        *(float4*)(c2s + oc0 * 132 + lane * 4) = make_float4(cv[0], cv[1], cv[2], cv[3]);
        *(float4*)(c2s + (oc0 + 1) * 132 + lane * 4) = make_float4(cv[4], cv[5], cv[6], cv[7]);
    }
    __syncthreads();

    if (tid < 256) {
        const int px = tid >> 1;
        const int ob = (tid & 1) * 12;
        ull acc[6];
        #pragma unroll
        for (int m = 0; m < 6; m++) acc[m] = 0ull;
        const float4* fea4 = (const float4*)(fea +
            ((size_t)b * NTOK + (size_t)y * W + px) * 64);
        #pragma unroll 4
        for (int c4 = 0; c4 < 16; c4++) {
            float4 f = fea4[c4];
            float fe[4] = {f.x, f.y, f.z, f.w};
            #pragma unroll
            for (int e = 0; e < 4; e++) {
                ull f2 = pack2(fe[e], fe[e]);
                const ulonglong2* wrow =
                    (const ulonglong2*)(W2s + (c4 * 4 + e) * 24 + ob);
                ulonglong2 wa = wrow[0];
                fma2(acc[0], wa.x, f2);
                fma2(acc[1], wa.y, f2);
                ulonglong2 wb = wrow[1];
                fma2(acc[2], wb.x, f2);
                fma2(acc[3], wb.y, f2);
                ulonglong2 wc = wrow[2];
                fma2(acc[4], wc.x, f2);
                fma2(acc[5], wc.y, f2);
            }
        }
        float res[12];
        #pragma unroll
        for (int m = 0; m < 6; m++) {
            float lo, hi; unpack2(acc[m], lo, hi);
            res[2 * m] = lo + bps[ob + 2 * m];
            res[2 * m + 1] = hi + bps[ob + 2 * m + 1];
        }
        #pragma unroll
        for (int ch = 0; ch < 12; ch++)
            res[ch] += c2s[(ob + ch) * 132 + px];
        float4* og = (float4*)(out +
            ((size_t)b * NTOK + (size_t)y * W + px) * 24 + ob);
        og[0] = make_float4(res[0], res[1], res[2], res[3]);
        og[1] = make_float4(res[4], res[5], res[6], res[7]);
        og[2] = make_float4(res[8], res[9], res[10], res[11]);
    }
}

// ===========================================================================
extern "C" void kernel_launch(void* const* d_in, const int* in_sizes, int n_in,
                              void* d_out, int out_size)
{
    const float* x = (const float*)d_in[0];
    const float* fea = (const float*)d_in[1];
    const float* im = (const float*)d_in[2];
    const float* Wq = (const float*)d_in[3];
    const float* Wk = (const float*)d_in[4];
    const float* Wv = (const float*)d_in[5];
    const float* rescale = (const float*)d_in[6];
    const float* Wp = (const float*)d_in[7];
    const float* bp = (const float*)d_in[8];
    const float* c1w = (const float*)d_in[9];
    const float* c2w = (const float*)d_in[10];
    float* out = (float*)d_out;

    k1_kinp_S<<<dim3(128, B), 256>>>(x, im, Wk);
    k4a_conv1_k2<<<dim3(130, B), 384>>>(c1w, fea, Wq, Wv, Wp, rescale);
    k4b_conv2_proj<<<dim3(128, B), 384>>>(fea, bp, c2w, out);
}